// round 5
// baseline (speedup 1.0000x reference)
#include <cuda_runtime.h>
#include <math.h>

#define BATCH 1024
#define DD 128
#define G3 384
#define TT 96
#define NSTEP 95
#define S_ODE 132
#define S_GRU 388

typedef unsigned long long u64;

__device__ __align__(256) float g_traj[(size_t)TT * BATCH * DD];
__device__ __align__(256) float g_gi[(size_t)TT * BATCH * G3];
__device__ __align__(256) float g_h1[(size_t)TT * BATCH * DD];
__device__ __align__(256) float g_h2[(size_t)BATCH * DD];

// ---- packed f32x2 + fast transcendental helpers ----
__device__ __forceinline__ u64 pack2(float lo, float hi) {
    u64 r; asm("mov.b64 %0,{%1,%2};" : "=l"(r) : "f"(lo), "f"(hi)); return r;
}
__device__ __forceinline__ u64 dup2(float v) { return pack2(v, v); }
__device__ __forceinline__ void unpk2(u64 v, float& lo, float& hi) {
    asm("mov.b64 {%0,%1},%2;" : "=f"(lo), "=f"(hi) : "l"(v));
}
__device__ __forceinline__ u64 ffma2(u64 a, u64 b, u64 c) {
    u64 d; asm("fma.rn.f32x2 %0,%1,%2,%3;" : "=l"(d) : "l"(a), "l"(b), "l"(c)); return d;
}
__device__ __forceinline__ u64 fadd2(u64 a, u64 b) {
    u64 d; asm("add.rn.f32x2 %0,%1,%2;" : "=l"(d) : "l"(a), "l"(b)); return d;
}
__device__ __forceinline__ float fex2(float x) { float r; asm("ex2.approx.f32 %0,%1;" : "=f"(r) : "f"(x)); return r; }
__device__ __forceinline__ float frcp(float x) { float r; asm("rcp.approx.f32 %0,%1;" : "=f"(r) : "f"(x)); return r; }
__device__ __forceinline__ float ftanh(float x) { return 1.0f - 2.0f * frcp(fex2(2.8853900817779268f * x) + 1.0f); }
__device__ __forceinline__ float fsigm(float x) { return frcp(1.0f + fex2(-1.4426950408889634f * x)); }

// ---------------------------------------------------------------------------
// Phase 1: Dopri5 ODE. 512 thr = 16 warps. Matvec role: warp (s = w>>1 k-slice
// of 16, rh = w&1 row-half of 4 rows). Reduce/RK role: warp owns (row = w>>1,
// jh = w&1 half of j). xs: [row][k] dup'd float2 pairs.
// ---------------------------------------------------------------------------
__device__ __forceinline__ void ode_mv(const float* __restrict__ Ws, const u64* xsu,
                                       float* part, int lane, int s, int rh,
                                       int row_m, int jh, float b0, float b1,
                                       float (&ko)[2])
{
    u64 acc[4][2];
#pragma unroll
    for (int r = 0; r < 4; r++) { acc[r][0] = pack2(0.f, 0.f); acc[r][1] = pack2(0.f, 0.f); }
    const int kbase = 16 * s;
#pragma unroll
    for (int kk = 0; kk < 16; kk += 2) {
        const int k = kbase + kk;
        const ulonglong2 x0 = *(const ulonglong2*)(xsu + (4 * rh + 0) * 128 + k);
        const ulonglong2 x1 = *(const ulonglong2*)(xsu + (4 * rh + 1) * 128 + k);
        const ulonglong2 x2 = *(const ulonglong2*)(xsu + (4 * rh + 2) * 128 + k);
        const ulonglong2 x3 = *(const ulonglong2*)(xsu + (4 * rh + 3) * 128 + k);
        const ulonglong2 wA = *(const ulonglong2*)(Ws + k * S_ODE + 4 * lane);
        const ulonglong2 wB = *(const ulonglong2*)(Ws + (k + 1) * S_ODE + 4 * lane);
        acc[0][0] = ffma2(x0.x, wA.x, acc[0][0]); acc[0][1] = ffma2(x0.x, wA.y, acc[0][1]);
        acc[1][0] = ffma2(x1.x, wA.x, acc[1][0]); acc[1][1] = ffma2(x1.x, wA.y, acc[1][1]);
        acc[2][0] = ffma2(x2.x, wA.x, acc[2][0]); acc[2][1] = ffma2(x2.x, wA.y, acc[2][1]);
        acc[3][0] = ffma2(x3.x, wA.x, acc[3][0]); acc[3][1] = ffma2(x3.x, wA.y, acc[3][1]);
        acc[0][0] = ffma2(x0.y, wB.x, acc[0][0]); acc[0][1] = ffma2(x0.y, wB.y, acc[0][1]);
        acc[1][0] = ffma2(x1.y, wB.x, acc[1][0]); acc[1][1] = ffma2(x1.y, wB.y, acc[1][1]);
        acc[2][0] = ffma2(x2.y, wB.x, acc[2][0]); acc[2][1] = ffma2(x2.y, wB.y, acc[2][1]);
        acc[3][0] = ffma2(x3.y, wB.x, acc[3][0]); acc[3][1] = ffma2(x3.y, wB.y, acc[3][1]);
    }
#pragma unroll
    for (int r = 0; r < 4; r++)
        *(ulonglong2*)(part + (size_t)((s * 8 + 4 * rh + r)) * 128 + 4 * lane) =
            make_ulonglong2(acc[r][0], acc[r][1]);
    __syncthreads();   // S1: all partials visible
    const float* rbase = part + (size_t)row_m * 128 + 64 * jh + 2 * lane;
    u64 ssum = *(const u64*)(rbase);
#pragma unroll
    for (int p = 1; p < 8; p++)
        ssum = fadd2(ssum, *(const u64*)(rbase + (size_t)p * 8 * 128));
    float f0, f1;
    unpk2(ssum, f0, f1);
    ko[0] = ftanh(f0 + b0);
    ko[1] = ftanh(f1 + b1);
}

__global__ void __launch_bounds__(512)
ode_kernel(const float* __restrict__ yl, const float* __restrict__ yh,
           const float* __restrict__ W, const float* __restrict__ bias)
{
    extern __shared__ float sm[];
    float* part = sm + S_ODE * DD;   // 8192 floats
    float* xsf  = part + 8192;       // 2048 floats
    u64* xsu = (u64*)xsf;
    const int tid = threadIdx.x;
    for (int idx = tid; idx < DD * DD; idx += 512) {
        const int j = idx >> 7, k = idx & 127;
        sm[k * S_ODE + j] = W[idx];
    }
    const int lane = tid & 31, w = tid >> 5;
    const int s = w >> 1, rh = w & 1;        // matvec role
    const int row_m = w >> 1, jh = w & 1;    // reduce/RK role
    const int row = blockIdx.x * 8 + row_m;
    const int e0 = 64 * jh + 2 * lane;

    const float b0 = bias[e0], b1 = bias[e0 + 1];

    float y[2];
#pragma unroll
    for (int m = 0; m < 2; m++) {
        const int e = e0 + m;
        y[m] = (e < 32) ? yl[row * 32 + e] : yh[row * 96 + (e - 32)];
    }
    *(float2*)(g_traj + (size_t)row * DD + e0) = make_float2(y[0], y[1]);
    float* xme = xsf + (size_t)row_m * 256 + e0 * 2;
    *(float4*)(xme) = make_float4(y[0], y[0], y[1], y[1]);
    __syncthreads();

    float k1[2], k2[2], k3[2], k4[2], k5[2], k6[2], ar[2];
    const float dt = 1.0f / 95.0f;

#define ODE_STORE_AR() do { \
    *(float4*)(xme) = make_float4(ar[0], ar[0], ar[1], ar[1]); \
    __syncthreads(); } while (0)

    for (int st = 0; st < NSTEP; st++) {
        ode_mv(sm, xsu, part, lane, s, rh, row_m, jh, b0, b1, k1);
#pragma unroll
        for (int m = 0; m < 2; m++) ar[m] = fmaf(dt * 0.2f, k1[m], y[m]);
        ODE_STORE_AR();

        ode_mv(sm, xsu, part, lane, s, rh, row_m, jh, b0, b1, k2);
#pragma unroll
        for (int m = 0; m < 2; m++) {
            float t = 0.075f * k1[m];
            t = fmaf(0.225f, k2[m], t);
            ar[m] = fmaf(dt, t, y[m]);
        }
        ODE_STORE_AR();

        ode_mv(sm, xsu, part, lane, s, rh, row_m, jh, b0, b1, k3);
#pragma unroll
        for (int m = 0; m < 2; m++) {
            float t = 0.9777777777777777f * k1[m];
            t = fmaf(-3.7333333333333334f, k2[m], t);
            t = fmaf(3.5555555555555554f, k3[m], t);
            ar[m] = fmaf(dt, t, y[m]);
        }
        ODE_STORE_AR();

        ode_mv(sm, xsu, part, lane, s, rh, row_m, jh, b0, b1, k4);
#pragma unroll
        for (int m = 0; m < 2; m++) {
            float t = 2.9525906892141633f * k1[m];
            t = fmaf(-11.595793324188385f, k2[m], t);
            t = fmaf(9.822892851699436f, k3[m], t);
            t = fmaf(-0.2908093278463649f, k4[m], t);
            ar[m] = fmaf(dt, t, y[m]);
        }
        ODE_STORE_AR();

        ode_mv(sm, xsu, part, lane, s, rh, row_m, jh, b0, b1, k5);
#pragma unroll
        for (int m = 0; m < 2; m++) {
            float t = 2.8462752525252526f * k1[m];
            t = fmaf(-10.757575757575758f, k2[m], t);
            t = fmaf(8.906422717743473f, k3[m], t);
            t = fmaf(0.2784090909090909f, k4[m], t);
            t = fmaf(-0.2735313036020583f, k5[m], t);
            ar[m] = fmaf(dt, t, y[m]);
        }
        ODE_STORE_AR();

        ode_mv(sm, xsu, part, lane, s, rh, row_m, jh, b0, b1, k6);
#pragma unroll
        for (int m = 0; m < 2; m++) {
            float t = 0.09114583333333333f * k1[m];
            t = fmaf(0.44923629829290207f, k3[m], t);
            t = fmaf(0.6510416666666666f, k4[m], t);
            t = fmaf(-0.322376179245283f, k5[m], t);
            t = fmaf(0.13095238095238096f, k6[m], t);
            y[m] = fmaf(dt, t, y[m]);
        }
        *(float4*)(xme) = make_float4(y[0], y[0], y[1], y[1]);
        *(float2*)(g_traj + ((size_t)(st + 1) * BATCH + row) * DD + e0) =
            make_float2(y[0], y[1]);
        __syncthreads();
    }
#undef ODE_STORE_AR
}

// ---------------------------------------------------------------------------
// Phase 2/4: gi = X @ W_ih^T + b_ih. 512 thr = 16 warps x 6 items, 8 iters.
// ---------------------------------------------------------------------------
__global__ void __launch_bounds__(512)
gi_kernel(const float* __restrict__ X, const float* __restrict__ Wih,
          const float* __restrict__ bih, float* __restrict__ gi)
{
    extern __shared__ float sm[];
    const int tid = threadIdx.x;
    for (int idx = tid; idx < G3 * DD; idx += 512) {
        const int j = idx >> 7, k = idx & 127;
        sm[k * S_GRU + j] = Wih[idx];
    }
    __syncthreads();

    const int lane = tid & 31, warp = tid >> 5;
    u64 bv[3][2];
#pragma unroll
    for (int g = 0; g < 3; g++) {
        bv[g][0] = pack2(bih[128 * g + 4 * lane], bih[128 * g + 4 * lane + 1]);
        bv[g][1] = pack2(bih[128 * g + 4 * lane + 2], bih[128 * g + 4 * lane + 3]);
    }
    const float* wb = sm + 4 * lane;

#pragma unroll 1
    for (int it = 0; it < 8; it++) {
        const int item = blockIdx.x * 768 + it * 96 + warp * 6;
        float a[6][4];
#pragma unroll
        for (int i = 0; i < 6; i++) {
            const float4 v = *(const float4*)(X + (size_t)(item + i) * DD + 4 * lane);
            a[i][0] = v.x; a[i][1] = v.y; a[i][2] = v.z; a[i][3] = v.w;
        }
        u64 acc[6][3][2];
#pragma unroll
        for (int i = 0; i < 6; i++)
#pragma unroll
            for (int g = 0; g < 3; g++) { acc[i][g][0] = bv[g][0]; acc[i][g][1] = bv[g][1]; }

#pragma unroll 1
        for (int kb = 0; kb < 32; kb++) {
#pragma unroll
            for (int mk = 0; mk < 4; mk++) {
                const int k = 4 * kb + mk;
                const ulonglong2 w0 = *(const ulonglong2*)(wb + k * S_GRU);
                const ulonglong2 w1 = *(const ulonglong2*)(wb + k * S_GRU + 128);
                const ulonglong2 w2 = *(const ulonglong2*)(wb + k * S_GRU + 256);
#pragma unroll
                for (int i = 0; i < 6; i++) {
                    const u64 xd = dup2(__shfl_sync(0xffffffffu, a[i][mk], kb));
                    acc[i][0][0] = ffma2(xd, w0.x, acc[i][0][0]);
                    acc[i][0][1] = ffma2(xd, w0.y, acc[i][0][1]);
                    acc[i][1][0] = ffma2(xd, w1.x, acc[i][1][0]);
                    acc[i][1][1] = ffma2(xd, w1.y, acc[i][1][1]);
                    acc[i][2][0] = ffma2(xd, w2.x, acc[i][2][0]);
                    acc[i][2][1] = ffma2(xd, w2.y, acc[i][2][1]);
                }
            }
        }
#pragma unroll
        for (int i = 0; i < 6; i++)
#pragma unroll
            for (int g = 0; g < 3; g++)
                *(ulonglong2*)(gi + (size_t)(item + i) * G3 + 128 * g + 4 * lane) =
                    make_ulonglong2(acc[i][g][0], acc[i][g][1]);
    }
}

// ---------------------------------------------------------------------------
// Phase 3/5: GRU scan. 768 thr = 24 warps = 4 row-groups(2 rows) x 3 gates x
// k-split-2. h dup'd in smem xs; (g==2,ks==0) warp per group finalizes 2 rows.
// ---------------------------------------------------------------------------
__global__ void __launch_bounds__(768)
gru_kernel(const float* __restrict__ gi, const float* __restrict__ Whh,
           const float* __restrict__ bhh, float* __restrict__ otraj,
           float* __restrict__ olast)
{
    extern __shared__ float sm[];
    float* pbuf = sm + DD * S_GRU;   // 3072 floats: [(gr*3+g)*2 + r][128]
    float* xsf  = pbuf + 3072;       // 2048 floats: [row(8)][k] dup pairs
    u64* xsu = (u64*)xsf;
    const int tid = threadIdx.x;
    for (int idx = tid; idx < G3 * DD; idx += 768) {
        const int j = idx >> 7, k = idx & 127;
        sm[k * S_GRU + j] = Whh[idx];
    }
    for (int idx = tid; idx < 2048; idx += 768) xsf[idx] = 0.0f;
    __syncthreads();

    const int lane = tid & 31, wid = tid >> 5;
    const int gr = wid / 6, rem = wid - gr * 6;
    const int g = rem >> 1, ks = rem & 1;
    const int row0 = blockIdx.x * 8 + gr * 2;

    u64 bv0 = pack2(0.f, 0.f), bv1 = bv0;
    if (ks == 0) {
        bv0 = pack2(bhh[g * 128 + 4 * lane], bhh[g * 128 + 4 * lane + 1]);
        bv1 = pack2(bhh[g * 128 + 4 * lane + 2], bhh[g * 128 + 4 * lane + 3]);
    }
    const float* wb = sm + g * 128 + 4 * lane;
    float* pme = pbuf + (size_t)((gr * 3 + g) * 2) * 128 + 4 * lane;

    float h[2][4];      // live only in (g==2, ks==0) warps
#pragma unroll
    for (int r = 0; r < 2; r++)
#pragma unroll
        for (int m = 0; m < 4; m++) h[r][m] = 0.0f;

    for (int t = 0; t < TT; t++) {
        float4 gvec[2];
        if (ks == 0) {
#pragma unroll
            for (int r = 0; r < 2; r++)
                gvec[r] = *(const float4*)(gi + ((size_t)t * BATCH + row0 + r) * G3 +
                                           g * 128 + 4 * lane);
        }
        u64 acc[2][2];
#pragma unroll
        for (int r = 0; r < 2; r++) { acc[r][0] = bv0; acc[r][1] = bv1; }

        const int kbase = 64 * ks;
#pragma unroll 8
        for (int kk = 0; kk < 64; kk += 2) {
            const int k = kbase + kk;
            const ulonglong2 x0 = *(const ulonglong2*)(xsu + (gr * 2 + 0) * 128 + k);
            const ulonglong2 x1 = *(const ulonglong2*)(xsu + (gr * 2 + 1) * 128 + k);
            const ulonglong2 wA = *(const ulonglong2*)(wb + k * S_GRU);
            const ulonglong2 wB = *(const ulonglong2*)(wb + (k + 1) * S_GRU);
            acc[0][0] = ffma2(x0.x, wA.x, acc[0][0]); acc[0][1] = ffma2(x0.x, wA.y, acc[0][1]);
            acc[1][0] = ffma2(x1.x, wA.x, acc[1][0]); acc[1][1] = ffma2(x1.x, wA.y, acc[1][1]);
            acc[0][0] = ffma2(x0.y, wB.x, acc[0][0]); acc[0][1] = ffma2(x0.y, wB.y, acc[0][1]);
            acc[1][0] = ffma2(x1.y, wB.x, acc[1][0]); acc[1][1] = ffma2(x1.y, wB.y, acc[1][1]);
        }
        if (ks == 1) {
#pragma unroll
            for (int r = 0; r < 2; r++)
                *(ulonglong2*)(pme + r * 128) = make_ulonglong2(acc[r][0], acc[r][1]);
        }
        __syncthreads();   // A: ks1 partials visible

        float np[2][4];
        if (ks == 0) {
#pragma unroll
            for (int r = 0; r < 2; r++) {
                const ulonglong2 p = *(const ulonglong2*)(pme + r * 128);
                const u64 s0 = fadd2(acc[r][0], p.x), s1 = fadd2(acc[r][1], p.y);
                float a0, a1, a2, a3;
                unpk2(s0, a0, a1); unpk2(s1, a2, a3);
                if (g < 2) {
                    *(float4*)(pme + r * 128) =
                        make_float4(fsigm(gvec[r].x + a0), fsigm(gvec[r].y + a1),
                                    fsigm(gvec[r].z + a2), fsigm(gvec[r].w + a3));
                } else {
                    np[r][0] = a0; np[r][1] = a1; np[r][2] = a2; np[r][3] = a3;
                }
            }
        }
        __syncthreads();   // B: r/z gate values visible

        if (ks == 0 && g == 2) {
            const float* rb = pbuf + (size_t)(gr * 3 + 0) * 2 * 128 + 4 * lane;
            const float* zb = pbuf + (size_t)(gr * 3 + 1) * 2 * 128 + 4 * lane;
#pragma unroll
            for (int r = 0; r < 2; r++) {
                const float4 rv = *(const float4*)(rb + r * 128);
                const float4 zv = *(const float4*)(zb + r * 128);
                const float n0 = ftanh(gvec[r].x + rv.x * np[r][0]);
                const float n1 = ftanh(gvec[r].y + rv.y * np[r][1]);
                const float n2 = ftanh(gvec[r].z + rv.z * np[r][2]);
                const float n3 = ftanh(gvec[r].w + rv.w * np[r][3]);
                h[r][0] = n0 + zv.x * (h[r][0] - n0);
                h[r][1] = n1 + zv.y * (h[r][1] - n1);
                h[r][2] = n2 + zv.z * (h[r][2] - n2);
                h[r][3] = n3 + zv.w * (h[r][3] - n3);
                float* xme = xsf + (size_t)((gr * 2 + r) * 128 + 4 * lane) * 2;
                *(float4*)(xme)     = make_float4(h[r][0], h[r][0], h[r][1], h[r][1]);
                *(float4*)(xme + 4) = make_float4(h[r][2], h[r][2], h[r][3], h[r][3]);
                if (otraj)
                    *(float4*)(otraj + ((size_t)t * BATCH + row0 + r) * DD + 4 * lane) =
                        make_float4(h[r][0], h[r][1], h[r][2], h[r][3]);
            }
        }
        __syncthreads();   // C: new h visible
    }
    if (olast && ks == 0 && g == 2) {
#pragma unroll
        for (int r = 0; r < 2; r++)
            *(float4*)(olast + (size_t)(row0 + r) * DD + 4 * lane) =
                make_float4(h[r][0], h[r][1], h[r][2], h[r][3]);
    }
}

// ---------------------------------------------------------------------------
// Phase 6: FC head (unchanged).
// ---------------------------------------------------------------------------
__global__ void __launch_bounds__(256)
fc_kernel(const float* __restrict__ W1, const float* __restrict__ b1,
          const float* __restrict__ W2, const float* __restrict__ b2,
          float* __restrict__ out)
{
    extern __shared__ float sm[];
    float* hs = sm;
    float* hd = sm + 1024;
    float* wt = sm + 1536;
    const int tid = threadIdx.x;
    const int row0 = blockIdx.x * 8;

    for (int idx = tid; idx < 8 * DD; idx += 256) hs[idx] = g_h2[(size_t)row0 * DD + idx];
    for (int idx = tid; idx < 64 * DD; idx += 256) {
        const int j = idx >> 7, k = idx & 127;
        wt[k * 68 + j] = W1[idx];
    }
    __syncthreads();

#pragma unroll
    for (int i = 0; i < 2; i++) {
        const int p = tid + 256 * i, r = p >> 6, j = p & 63;
        float acc = b1[j];
#pragma unroll 8
        for (int k = 0; k < DD; k++) acc = fmaf(hs[r * DD + k], wt[k * 68 + j], acc);
        hd[r * 64 + j] = acc * normcdff(acc);
    }

    for (int c = 0; c < 12; c++) {
        __syncthreads();
        for (int idx = tid; idx < 256 * 64; idx += 256) {
            const int jj = idx >> 6, k = idx & 63;
            wt[k * 260 + jj] = W2[(size_t)(c * 256 + jj) * 64 + k];
        }
        __syncthreads();
        const int j = c * 256 + tid;
        float acc[8];
#pragma unroll
        for (int r = 0; r < 8; r++) acc[r] = b2[j];
#pragma unroll 8
        for (int k = 0; k < 64; k++) {
            const float w = wt[k * 260 + tid];
#pragma unroll
            for (int r = 0; r < 8; r++) acc[r] = fmaf(hd[r * 64 + k], w, acc[r]);
        }
#pragma unroll
        for (int r = 0; r < 8; r++) out[(size_t)(row0 + r) * 3072 + j] = acc[r];
    }
}

// ---------------------------------------------------------------------------
extern "C" void kernel_launch(void* const* d_in, const int* in_sizes, int n_in,
                              void* d_out, int out_size)
{
    (void)in_sizes; (void)n_in; (void)out_size;
    const float* yl    = (const float*)d_in[1];
    const float* yh    = (const float*)d_in[2];
    const float* W_ode = (const float*)d_in[3];
    const float* b_ode = (const float*)d_in[4];
    const float* W_ih0 = (const float*)d_in[5];
    const float* W_hh0 = (const float*)d_in[6];
    const float* b_ih0 = (const float*)d_in[7];
    const float* b_hh0 = (const float*)d_in[8];
    const float* W_ih1 = (const float*)d_in[9];
    const float* W_hh1 = (const float*)d_in[10];
    const float* b_ih1 = (const float*)d_in[11];
    const float* b_hh1 = (const float*)d_in[12];
    const float* W1    = (const float*)d_in[13];
    const float* b1    = (const float*)d_in[14];
    const float* W2    = (const float*)d_in[15];
    const float* b2    = (const float*)d_in[16];
    float* out = (float*)d_out;

    float *traj, *gibuf, *h1, *h2;
    cudaGetSymbolAddress((void**)&traj,  g_traj);
    cudaGetSymbolAddress((void**)&gibuf, g_gi);
    cudaGetSymbolAddress((void**)&h1,    g_h1);
    cudaGetSymbolAddress((void**)&h2,    g_h2);

    const int SM_ODE = (S_ODE * DD + 8192 + 2048) * 4;   // 108,544 B
    const int SM_GI  = S_GRU * DD * 4;                   // 198,656 B
    const int SM_GRU2 = (S_GRU * DD + 3072 + 2048) * 4;  // 219,136 B
    const int SM_FC  = (1536 + 64 * 260) * 4;            //  72,704 B
    cudaFuncSetAttribute(ode_kernel, cudaFuncAttributeMaxDynamicSharedMemorySize, SM_ODE);
    cudaFuncSetAttribute(gi_kernel,  cudaFuncAttributeMaxDynamicSharedMemorySize, SM_GI);
    cudaFuncSetAttribute(gru_kernel, cudaFuncAttributeMaxDynamicSharedMemorySize, SM_GRU2);
    cudaFuncSetAttribute(fc_kernel,  cudaFuncAttributeMaxDynamicSharedMemorySize, SM_FC);

    ode_kernel<<<128, 512, SM_ODE>>>(yl, yh, W_ode, b_ode);
    gi_kernel <<<128, 512, SM_GI>>>(traj, W_ih0, b_ih0, gibuf);
    gru_kernel<<<128, 768, SM_GRU2>>>(gibuf, W_hh0, b_hh0, h1, nullptr);
    gi_kernel <<<128, 512, SM_GI>>>(h1, W_ih1, b_ih1, gibuf);
    gru_kernel<<<128, 768, SM_GRU2>>>(gibuf, W_hh1, b_hh1, nullptr, h2);
    fc_kernel <<<128, 256, SM_FC>>>(W1, b1, W2, b2, out);
}

// round 6
// speedup vs baseline: 1.1453x; 1.1453x over previous
#include <cuda_runtime.h>
#include <math.h>

#define BATCH 1024
#define DD 128
#define G3 384
#define TT 96
#define NSTEP 95
#define S_ODE 132
#define S_GRU 388

typedef unsigned long long u64;

__device__ __align__(256) float g_traj[(size_t)TT * BATCH * DD];
__device__ __align__(256) float g_gi[(size_t)TT * BATCH * G3];
__device__ __align__(256) float g_h1[(size_t)TT * BATCH * DD];
__device__ __align__(256) float g_h2[(size_t)BATCH * DD];

// ---- packed f32x2 + fast transcendental helpers ----
__device__ __forceinline__ u64 pack2(float lo, float hi) {
    u64 r; asm("mov.b64 %0,{%1,%2};" : "=l"(r) : "f"(lo), "f"(hi)); return r;
}
__device__ __forceinline__ u64 dup2(float v) { return pack2(v, v); }
__device__ __forceinline__ void unpk2(u64 v, float& lo, float& hi) {
    asm("mov.b64 {%0,%1},%2;" : "=f"(lo), "=f"(hi) : "l"(v));
}
__device__ __forceinline__ u64 ffma2(u64 a, u64 b, u64 c) {
    u64 d; asm("fma.rn.f32x2 %0,%1,%2,%3;" : "=l"(d) : "l"(a), "l"(b), "l"(c)); return d;
}
__device__ __forceinline__ u64 fadd2(u64 a, u64 b) {
    u64 d; asm("add.rn.f32x2 %0,%1,%2;" : "=l"(d) : "l"(a), "l"(b)); return d;
}
__device__ __forceinline__ float fex2(float x) { float r; asm("ex2.approx.f32 %0,%1;" : "=f"(r) : "f"(x)); return r; }
__device__ __forceinline__ float frcp(float x) { float r; asm("rcp.approx.f32 %0,%1;" : "=f"(r) : "f"(x)); return r; }
__device__ __forceinline__ float ftanh(float x) { return 1.0f - 2.0f * frcp(fex2(2.8853900817779268f * x) + 1.0f); }
__device__ __forceinline__ float fsigm(float x) { return frcp(1.0f + fex2(-1.4426950408889634f * x)); }

// ---------------------------------------------------------------------------
// Phase 1: Dopri5 ODE (exact R4 version). 256 thr = 2 row-groups x 4 k-slices.
// ---------------------------------------------------------------------------
__device__ __forceinline__ void ode_mv(const float* __restrict__ Ws, const u64* xsu,
                                       float* part, const float (&bv)[4],
                                       int lane, int gr, int q, float (&ko)[4])
{
    u64 acc[4][2];
#pragma unroll
    for (int r = 0; r < 4; r++) { acc[r][0] = pack2(0.f, 0.f); acc[r][1] = pack2(0.f, 0.f); }
    const int kbase = 32 * q;
#pragma unroll 4
    for (int kk = 0; kk < 32; kk += 2) {
        const int k = kbase + kk;
        const ulonglong2 x0 = *(const ulonglong2*)(xsu + (gr * 4 + 0) * 128 + k);
        const ulonglong2 x1 = *(const ulonglong2*)(xsu + (gr * 4 + 1) * 128 + k);
        const ulonglong2 x2 = *(const ulonglong2*)(xsu + (gr * 4 + 2) * 128 + k);
        const ulonglong2 x3 = *(const ulonglong2*)(xsu + (gr * 4 + 3) * 128 + k);
        const ulonglong2 wA = *(const ulonglong2*)(Ws + k * S_ODE + 4 * lane);
        const ulonglong2 wB = *(const ulonglong2*)(Ws + (k + 1) * S_ODE + 4 * lane);
        acc[0][0] = ffma2(x0.x, wA.x, acc[0][0]); acc[0][1] = ffma2(x0.x, wA.y, acc[0][1]);
        acc[1][0] = ffma2(x1.x, wA.x, acc[1][0]); acc[1][1] = ffma2(x1.x, wA.y, acc[1][1]);
        acc[2][0] = ffma2(x2.x, wA.x, acc[2][0]); acc[2][1] = ffma2(x2.x, wA.y, acc[2][1]);
        acc[3][0] = ffma2(x3.x, wA.x, acc[3][0]); acc[3][1] = ffma2(x3.x, wA.y, acc[3][1]);
        acc[0][0] = ffma2(x0.y, wB.x, acc[0][0]); acc[0][1] = ffma2(x0.y, wB.y, acc[0][1]);
        acc[1][0] = ffma2(x1.y, wB.x, acc[1][0]); acc[1][1] = ffma2(x1.y, wB.y, acc[1][1]);
        acc[2][0] = ffma2(x2.y, wB.x, acc[2][0]); acc[2][1] = ffma2(x2.y, wB.y, acc[2][1]);
        acc[3][0] = ffma2(x3.y, wB.x, acc[3][0]); acc[3][1] = ffma2(x3.y, wB.y, acc[3][1]);
    }
    float* pme = part + (size_t)((gr * 4 + q) * 4) * 128 + 4 * lane;
#pragma unroll
    for (int r = 0; r < 4; r++)
        *(ulonglong2*)(pme + r * 128) = make_ulonglong2(acc[r][0], acc[r][1]);
    __syncthreads();   // S1
    u64 s0 = acc[q][0], s1 = acc[q][1];
#pragma unroll
    for (int p = 0; p < 4; p++) {
        if (p == q) continue;
        const ulonglong2 v = *(const ulonglong2*)(part + (size_t)((gr * 4 + p) * 4 + q) * 128 + 4 * lane);
        s0 = fadd2(s0, v.x); s1 = fadd2(s1, v.y);
    }
    float f0, f1, f2, f3;
    unpk2(s0, f0, f1); unpk2(s1, f2, f3);
    ko[0] = ftanh(f0 + bv[0]); ko[1] = ftanh(f1 + bv[1]);
    ko[2] = ftanh(f2 + bv[2]); ko[3] = ftanh(f3 + bv[3]);
}

__global__ void __launch_bounds__(256)
ode_kernel(const float* __restrict__ yl, const float* __restrict__ yh,
           const float* __restrict__ W, const float* __restrict__ bias)
{
    extern __shared__ float sm[];
    float* part = sm + S_ODE * DD;
    float* xsf  = part + 4096;
    u64* xsu = (u64*)xsf;
    const int tid = threadIdx.x;
    for (int idx = tid; idx < DD * DD; idx += 256) {
        const int j = idx >> 7, k = idx & 127;
        sm[k * S_ODE + j] = W[idx];
    }
    const int lane = tid & 31, warp = tid >> 5;
    const int gr = warp >> 2, q = warp & 3;
    const int row = blockIdx.x * 8 + gr * 4 + q;

    float bv[4];
#pragma unroll
    for (int m = 0; m < 4; m++) bv[m] = bias[4 * lane + m];

    float y[4];
#pragma unroll
    for (int m = 0; m < 4; m++) {
        const int e = 4 * lane + m;
        y[m] = (e < 32) ? yl[row * 32 + e] : yh[row * 96 + (e - 32)];
    }
    *(float4*)(g_traj + (size_t)row * DD + 4 * lane) = make_float4(y[0], y[1], y[2], y[3]);
    float* xme = xsf + (size_t)((gr * 4 + q) * 128 + 4 * lane) * 2;
    *(float4*)(xme)     = make_float4(y[0], y[0], y[1], y[1]);
    *(float4*)(xme + 4) = make_float4(y[2], y[2], y[3], y[3]);
    __syncthreads();

    float k1[4], k2[4], k3[4], k4[4], k5[4], k6[4], ar[4];
    const float dt = 1.0f / 95.0f;

#define ODE_STORE_AR() do { \
    *(float4*)(xme)     = make_float4(ar[0], ar[0], ar[1], ar[1]); \
    *(float4*)(xme + 4) = make_float4(ar[2], ar[2], ar[3], ar[3]); \
    __syncthreads(); } while (0)

    for (int st = 0; st < NSTEP; st++) {
        ode_mv(sm, xsu, part, bv, lane, gr, q, k1);
#pragma unroll
        for (int m = 0; m < 4; m++) ar[m] = fmaf(dt * 0.2f, k1[m], y[m]);
        ODE_STORE_AR();

        ode_mv(sm, xsu, part, bv, lane, gr, q, k2);
#pragma unroll
        for (int m = 0; m < 4; m++) {
            float s = 0.075f * k1[m];
            s = fmaf(0.225f, k2[m], s);
            ar[m] = fmaf(dt, s, y[m]);
        }
        ODE_STORE_AR();

        ode_mv(sm, xsu, part, bv, lane, gr, q, k3);
#pragma unroll
        for (int m = 0; m < 4; m++) {
            float s = 0.9777777777777777f * k1[m];
            s = fmaf(-3.7333333333333334f, k2[m], s);
            s = fmaf(3.5555555555555554f, k3[m], s);
            ar[m] = fmaf(dt, s, y[m]);
        }
        ODE_STORE_AR();

        ode_mv(sm, xsu, part, bv, lane, gr, q, k4);
#pragma unroll
        for (int m = 0; m < 4; m++) {
            float s = 2.9525906892141633f * k1[m];
            s = fmaf(-11.595793324188385f, k2[m], s);
            s = fmaf(9.822892851699436f, k3[m], s);
            s = fmaf(-0.2908093278463649f, k4[m], s);
            ar[m] = fmaf(dt, s, y[m]);
        }
        ODE_STORE_AR();

        ode_mv(sm, xsu, part, bv, lane, gr, q, k5);
#pragma unroll
        for (int m = 0; m < 4; m++) {
            float s = 2.8462752525252526f * k1[m];
            s = fmaf(-10.757575757575758f, k2[m], s);
            s = fmaf(8.906422717743473f, k3[m], s);
            s = fmaf(0.2784090909090909f, k4[m], s);
            s = fmaf(-0.2735313036020583f, k5[m], s);
            ar[m] = fmaf(dt, s, y[m]);
        }
        ODE_STORE_AR();

        ode_mv(sm, xsu, part, bv, lane, gr, q, k6);
#pragma unroll
        for (int m = 0; m < 4; m++) {
            float s = 0.09114583333333333f * k1[m];
            s = fmaf(0.44923629829290207f, k3[m], s);
            s = fmaf(0.6510416666666666f, k4[m], s);
            s = fmaf(-0.322376179245283f, k5[m], s);
            s = fmaf(0.13095238095238096f, k6[m], s);
            y[m] = fmaf(dt, s, y[m]);
        }
        *(float4*)(xme)     = make_float4(y[0], y[0], y[1], y[1]);
        *(float4*)(xme + 4) = make_float4(y[2], y[2], y[3], y[3]);
        *(float4*)(g_traj + ((size_t)(st + 1) * BATCH + row) * DD + 4 * lane) =
            make_float4(y[0], y[1], y[2], y[3]);
        __syncthreads();
    }
#undef ODE_STORE_AR
}

// ---------------------------------------------------------------------------
// Phase 2/4: gi = X @ W_ih^T + b_ih (exact R4 version). 512 thr x 4 items.
// ---------------------------------------------------------------------------
__global__ void __launch_bounds__(512)
gi_kernel(const float* __restrict__ X, const float* __restrict__ Wih,
          const float* __restrict__ bih, float* __restrict__ gi)
{
    extern __shared__ float sm[];
    const int tid = threadIdx.x;
    for (int idx = tid; idx < G3 * DD; idx += 512) {
        const int j = idx >> 7, k = idx & 127;
        sm[k * S_GRU + j] = Wih[idx];
    }
    __syncthreads();

    const int lane = tid & 31, warp = tid >> 5;
    u64 bv[3][2];
#pragma unroll
    for (int g = 0; g < 3; g++) {
        bv[g][0] = pack2(bih[128 * g + 4 * lane], bih[128 * g + 4 * lane + 1]);
        bv[g][1] = pack2(bih[128 * g + 4 * lane + 2], bih[128 * g + 4 * lane + 3]);
    }
    const float* wb = sm + 4 * lane;

#pragma unroll 1
    for (int it = 0; it < 12; it++) {
        const int item = blockIdx.x * 768 + it * 64 + warp * 4;
        float a[4][4];
#pragma unroll
        for (int i = 0; i < 4; i++) {
            const float4 v = *(const float4*)(X + (size_t)(item + i) * DD + 4 * lane);
            a[i][0] = v.x; a[i][1] = v.y; a[i][2] = v.z; a[i][3] = v.w;
        }
        u64 acc[4][3][2];
#pragma unroll
        for (int i = 0; i < 4; i++)
#pragma unroll
            for (int g = 0; g < 3; g++) { acc[i][g][0] = bv[g][0]; acc[i][g][1] = bv[g][1]; }

#pragma unroll 2
        for (int kb = 0; kb < 32; kb++) {
#pragma unroll
            for (int mk = 0; mk < 4; mk++) {
                const int k = 4 * kb + mk;
                const ulonglong2 w0 = *(const ulonglong2*)(wb + k * S_GRU);
                const ulonglong2 w1 = *(const ulonglong2*)(wb + k * S_GRU + 128);
                const ulonglong2 w2 = *(const ulonglong2*)(wb + k * S_GRU + 256);
#pragma unroll
                for (int i = 0; i < 4; i++) {
                    const u64 xd = dup2(__shfl_sync(0xffffffffu, a[i][mk], kb));
                    acc[i][0][0] = ffma2(xd, w0.x, acc[i][0][0]);
                    acc[i][0][1] = ffma2(xd, w0.y, acc[i][0][1]);
                    acc[i][1][0] = ffma2(xd, w1.x, acc[i][1][0]);
                    acc[i][1][1] = ffma2(xd, w1.y, acc[i][1][1]);
                    acc[i][2][0] = ffma2(xd, w2.x, acc[i][2][0]);
                    acc[i][2][1] = ffma2(xd, w2.y, acc[i][2][1]);
                }
            }
        }
#pragma unroll
        for (int i = 0; i < 4; i++)
#pragma unroll
            for (int g = 0; g < 3; g++)
                *(ulonglong2*)(gi + (size_t)(item + i) * G3 + 128 * g + 4 * lane) =
                    make_ulonglong2(acc[i][g][0], acc[i][g][1]);
    }
}

// ---------------------------------------------------------------------------
// Phase 3/5: GRU scan, 2-barrier version. 384 thr = 12 warps.
// Matvec role: warp = (g, ks, rh): gate g, k-half ks, rows rh*4..rh*4+3 (raw
// partials, no bias). Finalize role: warps 0-7 each own one row: read 6
// partials, full gate math (bias folded here), write dup'd h + otraj.
// ---------------------------------------------------------------------------
__global__ void __launch_bounds__(384)
gru_kernel(const float* __restrict__ gi, const float* __restrict__ Whh,
           const float* __restrict__ bhh, float* __restrict__ otraj,
           float* __restrict__ olast)
{
    extern __shared__ float sm[];
    float* pbuf = sm + DD * S_GRU;   // 6144 floats: [(g*2+ks)*8 + row][128]
    float* xsf  = pbuf + 6144;       // 2048 floats: [row(8)][k] dup pairs
    u64* xsu = (u64*)xsf;
    const int tid = threadIdx.x;
    for (int idx = tid; idx < G3 * DD; idx += 384) {
        const int j = idx >> 7, k = idx & 127;
        sm[k * S_GRU + j] = Whh[idx];
    }
    for (int idx = tid; idx < 2048; idx += 384) xsf[idx] = 0.0f;
    __syncthreads();

    const int lane = tid & 31, wid = tid >> 5;
    // matvec role
    const int g = wid >> 2, ks = (wid >> 1) & 1, rh = wid & 1;
    const float* wb = sm + g * 128 + 4 * lane;
    float* pme = pbuf + (size_t)((g * 2 + ks) * 8 + rh * 4) * 128 + 4 * lane;
    // finalize role (warps 0..7)
    const int frow = wid;
    const bool fin = (wid < 8);
    const int grow = blockIdx.x * 8 + frow;

    float br[4], bz[4], bn[4];
    if (fin) {
        const float4 vr = *(const float4*)(bhh + 4 * lane);
        const float4 vz = *(const float4*)(bhh + 128 + 4 * lane);
        const float4 vn = *(const float4*)(bhh + 256 + 4 * lane);
        br[0]=vr.x; br[1]=vr.y; br[2]=vr.z; br[3]=vr.w;
        bz[0]=vz.x; bz[1]=vz.y; bz[2]=vz.z; bz[3]=vz.w;
        bn[0]=vn.x; bn[1]=vn.y; bn[2]=vn.z; bn[3]=vn.w;
    }
    float h[4] = {0.f, 0.f, 0.f, 0.f};

    for (int t = 0; t < TT; t++) {
        float4 gr_, gz_, gn_;
        if (fin) {
            const float* gp = gi + ((size_t)t * BATCH + grow) * G3 + 4 * lane;
            gr_ = *(const float4*)(gp);
            gz_ = *(const float4*)(gp + 128);
            gn_ = *(const float4*)(gp + 256);
        }
        // matvec: gate g, 4 rows, k-half ks — raw partials
        u64 acc[4][2];
#pragma unroll
        for (int r = 0; r < 4; r++) { acc[r][0] = pack2(0.f, 0.f); acc[r][1] = pack2(0.f, 0.f); }
        const int kbase = 64 * ks;
#pragma unroll 8
        for (int kk = 0; kk < 64; kk += 2) {
            const int k = kbase + kk;
            const ulonglong2 x0 = *(const ulonglong2*)(xsu + (rh * 4 + 0) * 128 + k);
            const ulonglong2 x1 = *(const ulonglong2*)(xsu + (rh * 4 + 1) * 128 + k);
            const ulonglong2 x2 = *(const ulonglong2*)(xsu + (rh * 4 + 2) * 128 + k);
            const ulonglong2 x3 = *(const ulonglong2*)(xsu + (rh * 4 + 3) * 128 + k);
            const ulonglong2 wA = *(const ulonglong2*)(wb + k * S_GRU);
            const ulonglong2 wB = *(const ulonglong2*)(wb + (k + 1) * S_GRU);
            acc[0][0] = ffma2(x0.x, wA.x, acc[0][0]); acc[0][1] = ffma2(x0.x, wA.y, acc[0][1]);
            acc[1][0] = ffma2(x1.x, wA.x, acc[1][0]); acc[1][1] = ffma2(x1.x, wA.y, acc[1][1]);
            acc[2][0] = ffma2(x2.x, wA.x, acc[2][0]); acc[2][1] = ffma2(x2.x, wA.y, acc[2][1]);
            acc[3][0] = ffma2(x3.x, wA.x, acc[3][0]); acc[3][1] = ffma2(x3.x, wA.y, acc[3][1]);
            acc[0][0] = ffma2(x0.y, wB.x, acc[0][0]); acc[0][1] = ffma2(x0.y, wB.y, acc[0][1]);
            acc[1][0] = ffma2(x1.y, wB.x, acc[1][0]); acc[1][1] = ffma2(x1.y, wB.y, acc[1][1]);
            acc[2][0] = ffma2(x2.y, wB.x, acc[2][0]); acc[2][1] = ffma2(x2.y, wB.y, acc[2][1]);
            acc[3][0] = ffma2(x3.y, wB.x, acc[3][0]); acc[3][1] = ffma2(x3.y, wB.y, acc[3][1]);
        }
#pragma unroll
        for (int r = 0; r < 4; r++)
            *(ulonglong2*)(pme + r * 128) = make_ulonglong2(acc[r][0], acc[r][1]);
        __syncthreads();   // A: all partials visible

        if (fin) {
            const float* pb = pbuf + (size_t)frow * 128 + 4 * lane;
            const ulonglong2 pr0 = *(const ulonglong2*)(pb);
            const ulonglong2 pr1 = *(const ulonglong2*)(pb + 8 * 128);
            const ulonglong2 pz0 = *(const ulonglong2*)(pb + 16 * 128);
            const ulonglong2 pz1 = *(const ulonglong2*)(pb + 24 * 128);
            const ulonglong2 pn0 = *(const ulonglong2*)(pb + 32 * 128);
            const ulonglong2 pn1 = *(const ulonglong2*)(pb + 40 * 128);
            float ar[4], az[4], an[4];
            {
                const u64 s0 = fadd2(pr0.x, pr1.x), s1 = fadd2(pr0.y, pr1.y);
                unpk2(s0, ar[0], ar[1]); unpk2(s1, ar[2], ar[3]);
            }
            {
                const u64 s0 = fadd2(pz0.x, pz1.x), s1 = fadd2(pz0.y, pz1.y);
                unpk2(s0, az[0], az[1]); unpk2(s1, az[2], az[3]);
            }
            {
                const u64 s0 = fadd2(pn0.x, pn1.x), s1 = fadd2(pn0.y, pn1.y);
                unpk2(s0, an[0], an[1]); unpk2(s1, an[2], an[3]);
            }
            const float gvr[4] = {gr_.x, gr_.y, gr_.z, gr_.w};
            const float gvz[4] = {gz_.x, gz_.y, gz_.z, gz_.w};
            const float gvn[4] = {gn_.x, gn_.y, gn_.z, gn_.w};
#pragma unroll
            for (int m = 0; m < 4; m++) {
                const float rg = fsigm(gvr[m] + ar[m] + br[m]);
                const float zg = fsigm(gvz[m] + az[m] + bz[m]);
                const float ng = ftanh(gvn[m] + rg * (an[m] + bn[m]));
                h[m] = ng + zg * (h[m] - ng);
            }
            float* xme = xsf + (size_t)(frow * 128 + 4 * lane) * 2;
            *(float4*)(xme)     = make_float4(h[0], h[0], h[1], h[1]);
            *(float4*)(xme + 4) = make_float4(h[2], h[2], h[3], h[3]);
            if (otraj)
                *(float4*)(otraj + ((size_t)t * BATCH + grow) * DD + 4 * lane) =
                    make_float4(h[0], h[1], h[2], h[3]);
        }
        __syncthreads();   // C: new h visible
    }
    if (olast && fin)
        *(float4*)(olast + (size_t)grow * DD + 4 * lane) =
            make_float4(h[0], h[1], h[2], h[3]);
}

// ---------------------------------------------------------------------------
// Phase 6: FC head (unchanged).
// ---------------------------------------------------------------------------
__global__ void __launch_bounds__(256)
fc_kernel(const float* __restrict__ W1, const float* __restrict__ b1,
          const float* __restrict__ W2, const float* __restrict__ b2,
          float* __restrict__ out)
{
    extern __shared__ float sm[];
    float* hs = sm;
    float* hd = sm + 1024;
    float* wt = sm + 1536;
    const int tid = threadIdx.x;
    const int row0 = blockIdx.x * 8;

    for (int idx = tid; idx < 8 * DD; idx += 256) hs[idx] = g_h2[(size_t)row0 * DD + idx];
    for (int idx = tid; idx < 64 * DD; idx += 256) {
        const int j = idx >> 7, k = idx & 127;
        wt[k * 68 + j] = W1[idx];
    }
    __syncthreads();

#pragma unroll
    for (int i = 0; i < 2; i++) {
        const int p = tid + 256 * i, r = p >> 6, j = p & 63;
        float acc = b1[j];
#pragma unroll 8
        for (int k = 0; k < DD; k++) acc = fmaf(hs[r * DD + k], wt[k * 68 + j], acc);
        hd[r * 64 + j] = acc * normcdff(acc);
    }

    for (int c = 0; c < 12; c++) {
        __syncthreads();
        for (int idx = tid; idx < 256 * 64; idx += 256) {
            const int jj = idx >> 6, k = idx & 63;
            wt[k * 260 + jj] = W2[(size_t)(c * 256 + jj) * 64 + k];
        }
        __syncthreads();
        const int j = c * 256 + tid;
        float acc[8];
#pragma unroll
        for (int r = 0; r < 8; r++) acc[r] = b2[j];
#pragma unroll 8
        for (int k = 0; k < 64; k++) {
            const float w = wt[k * 260 + tid];
#pragma unroll
            for (int r = 0; r < 8; r++) acc[r] = fmaf(hd[r * 64 + k], w, acc[r]);
        }
#pragma unroll
        for (int r = 0; r < 8; r++) out[(size_t)(row0 + r) * 3072 + j] = acc[r];
    }
}

// ---------------------------------------------------------------------------
extern "C" void kernel_launch(void* const* d_in, const int* in_sizes, int n_in,
                              void* d_out, int out_size)
{
    (void)in_sizes; (void)n_in; (void)out_size;
    const float* yl    = (const float*)d_in[1];
    const float* yh    = (const float*)d_in[2];
    const float* W_ode = (const float*)d_in[3];
    const float* b_ode = (const float*)d_in[4];
    const float* W_ih0 = (const float*)d_in[5];
    const float* W_hh0 = (const float*)d_in[6];
    const float* b_ih0 = (const float*)d_in[7];
    const float* b_hh0 = (const float*)d_in[8];
    const float* W_ih1 = (const float*)d_in[9];
    const float* W_hh1 = (const float*)d_in[10];
    const float* b_ih1 = (const float*)d_in[11];
    const float* b_hh1 = (const float*)d_in[12];
    const float* W1    = (const float*)d_in[13];
    const float* b1    = (const float*)d_in[14];
    const float* W2    = (const float*)d_in[15];
    const float* b2    = (const float*)d_in[16];
    float* out = (float*)d_out;

    float *traj, *gibuf, *h1, *h2;
    cudaGetSymbolAddress((void**)&traj,  g_traj);
    cudaGetSymbolAddress((void**)&gibuf, g_gi);
    cudaGetSymbolAddress((void**)&h1,    g_h1);
    cudaGetSymbolAddress((void**)&h2,    g_h2);

    const int SM_ODE  = (S_ODE * DD + 4096 + 2048) * 4;   //  92,160 B
    const int SM_GI   = S_GRU * DD * 4;                   // 198,656 B
    const int SM_GRU2 = (S_GRU * DD + 6144 + 2048) * 4;   // 231,424 B
    const int SM_FC   = (1536 + 64 * 260) * 4;            //  72,704 B
    cudaFuncSetAttribute(ode_kernel, cudaFuncAttributeMaxDynamicSharedMemorySize, SM_ODE);
    cudaFuncSetAttribute(gi_kernel,  cudaFuncAttributeMaxDynamicSharedMemorySize, SM_GI);
    cudaFuncSetAttribute(gru_kernel, cudaFuncAttributeMaxDynamicSharedMemorySize, SM_GRU2);
    cudaFuncSetAttribute(fc_kernel,  cudaFuncAttributeMaxDynamicSharedMemorySize, SM_FC);

    ode_kernel<<<128, 256, SM_ODE>>>(yl, yh, W_ode, b_ode);
    gi_kernel <<<128, 512, SM_GI>>>(traj, W_ih0, b_ih0, gibuf);
    gru_kernel<<<128, 384, SM_GRU2>>>(gibuf, W_hh0, b_hh0, h1, nullptr);
    gi_kernel <<<128, 512, SM_GI>>>(h1, W_ih1, b_ih1, gibuf);
    gru_kernel<<<128, 384, SM_GRU2>>>(gibuf, W_hh1, b_hh1, nullptr, h2);
    fc_kernel <<<128, 256, SM_FC>>>(W1, b1, W2, b2, out);
}

// round 7
// speedup vs baseline: 1.2794x; 1.1171x over previous
#include <cuda_runtime.h>
#include <math.h>

#define BATCH 1024
#define DD 128
#define G3 384
#define TT 96
#define NSTEP 95
#define S_ODE 132
#define S_GRU 388

typedef unsigned long long u64;

__device__ __align__(256) float g_traj[(size_t)TT * BATCH * DD];
__device__ __align__(256) float g_gi[(size_t)TT * BATCH * G3];
__device__ __align__(256) float g_h1[(size_t)TT * BATCH * DD];
__device__ __align__(256) float g_h2[(size_t)BATCH * DD];

// ---- packed f32x2 + fast transcendental helpers ----
__device__ __forceinline__ u64 pack2(float lo, float hi) {
    u64 r; asm("mov.b64 %0,{%1,%2};" : "=l"(r) : "f"(lo), "f"(hi)); return r;
}
__device__ __forceinline__ u64 dup2(float v) { return pack2(v, v); }
__device__ __forceinline__ void unpk2(u64 v, float& lo, float& hi) {
    asm("mov.b64 {%0,%1},%2;" : "=f"(lo), "=f"(hi) : "l"(v));
}
__device__ __forceinline__ u64 ffma2(u64 a, u64 b, u64 c) {
    u64 d; asm("fma.rn.f32x2 %0,%1,%2,%3;" : "=l"(d) : "l"(a), "l"(b), "l"(c)); return d;
}
__device__ __forceinline__ u64 fadd2(u64 a, u64 b) {
    u64 d; asm("add.rn.f32x2 %0,%1,%2;" : "=l"(d) : "l"(a), "l"(b)); return d;
}
__device__ __forceinline__ float fex2(float x) { float r; asm("ex2.approx.f32 %0,%1;" : "=f"(r) : "f"(x)); return r; }
__device__ __forceinline__ float frcp(float x) { float r; asm("rcp.approx.f32 %0,%1;" : "=f"(r) : "f"(x)); return r; }
__device__ __forceinline__ float ftanh(float x) { return 1.0f - 2.0f * frcp(fex2(2.8853900817779268f * x) + 1.0f); }
__device__ __forceinline__ float fsigm(float x) { return frcp(1.0f + fex2(-1.4426950408889634f * x)); }
__device__ __forceinline__ u64 tanh2(u64 v) {
    float a, b; unpk2(v, a, b); return pack2(ftanh(a), ftanh(b));
}

// ---------------------------------------------------------------------------
// Phase 1: Dopri5 ODE, row-pair f32x2 design. 256 thr = 8 warps.
// Matvec role: warp q does k-slice [16q,16q+16) for all 8 rows as 4 pairs;
// weights dup'd from registers, x-pairs broadcast from smem.
// Finalize role: warp (p = w>>1, jh = w&1) owns row-pair p, j-half jh:
// reduce 8 partials, tanh, RK (all in f32x2), store xs/g_traj.
// ---------------------------------------------------------------------------
__global__ void __launch_bounds__(256)
ode_kernel(const float* __restrict__ yl, const float* __restrict__ yh,
           const float* __restrict__ W, const float* __restrict__ bias)
{
    extern __shared__ float sm[];
    u64* pbuf = (u64*)(sm + S_ODE * DD);   // [q][p][j] u64: 8*4*128 = 32KB
    u64* xs   = pbuf + 4096;               // [p][k] u64 pairs: 4*128 = 4KB
    const int tid = threadIdx.x;
    for (int idx = tid; idx < DD * DD; idx += 256) {
        const int j = idx >> 7, k = idx & 127;
        sm[k * S_ODE + j] = W[idx];
    }
    const int lane = tid & 31, w = tid >> 5;
    const int q = w;                       // matvec k-slice
    const int p = w >> 1, jh = w & 1;      // finalize role
    const int j0 = 64 * jh + 2 * lane;
    const int rowA = blockIdx.x * 8 + 2 * p, rowB = rowA + 1;

    const u64 bv0 = dup2(bias[j0]), bv1 = dup2(bias[j0 + 1]);

    // init y pairs (u64 = (rowA, rowB) at one j)
    float a0 = (j0 < 32) ? yl[rowA * 32 + j0] : yh[rowA * 96 + j0 - 32];
    float b0 = (j0 < 32) ? yl[rowB * 32 + j0] : yh[rowB * 96 + j0 - 32];
    float a1 = (j0 + 1 < 32) ? yl[rowA * 32 + j0 + 1] : yh[rowA * 96 + j0 + 1 - 32];
    float b1 = (j0 + 1 < 32) ? yl[rowB * 32 + j0 + 1] : yh[rowB * 96 + j0 + 1 - 32];
    u64 y0 = pack2(a0, b0), y1 = pack2(a1, b1);
    *(float2*)(g_traj + (size_t)rowA * DD + j0) = make_float2(a0, a1);
    *(float2*)(g_traj + (size_t)rowB * DD + j0) = make_float2(b0, b1);
    *(ulonglong2*)(xs + p * 128 + j0) = make_ulonglong2(y0, y1);
    __syncthreads();

    const u64 dt2 = dup2(1.0f / 95.0f);
    u64 k1[2], k2[2], k3[2], k4[2], k5[2], k6[2], ar[2];

    // matvec + reduce, producing tanh'd pair values for (p, jh)
#define ODE_EVAL(KOUT) do { \
    u64 acc[4][4]; \
    _Pragma("unroll") \
    for (int pp = 0; pp < 4; pp++) { acc[pp][0]=0; acc[pp][1]=0; acc[pp][2]=0; acc[pp][3]=0; } \
    _Pragma("unroll") \
    for (int kk = 0; kk < 16; kk++) { \
        const int k = 16 * q + kk; \
        const float4 wv = *(const float4*)(sm + k * S_ODE + 4 * lane); \
        const u64 w0 = dup2(wv.x), w1 = dup2(wv.y), w2 = dup2(wv.z), w3 = dup2(wv.w); \
        const u64 x0 = xs[k], x1 = xs[128 + k], x2 = xs[256 + k], x3 = xs[384 + k]; \
        acc[0][0]=ffma2(x0,w0,acc[0][0]); acc[0][1]=ffma2(x0,w1,acc[0][1]); \
        acc[0][2]=ffma2(x0,w2,acc[0][2]); acc[0][3]=ffma2(x0,w3,acc[0][3]); \
        acc[1][0]=ffma2(x1,w0,acc[1][0]); acc[1][1]=ffma2(x1,w1,acc[1][1]); \
        acc[1][2]=ffma2(x1,w2,acc[1][2]); acc[1][3]=ffma2(x1,w3,acc[1][3]); \
        acc[2][0]=ffma2(x2,w0,acc[2][0]); acc[2][1]=ffma2(x2,w1,acc[2][1]); \
        acc[2][2]=ffma2(x2,w2,acc[2][2]); acc[2][3]=ffma2(x2,w3,acc[2][3]); \
        acc[3][0]=ffma2(x3,w0,acc[3][0]); acc[3][1]=ffma2(x3,w1,acc[3][1]); \
        acc[3][2]=ffma2(x3,w2,acc[3][2]); acc[3][3]=ffma2(x3,w3,acc[3][3]); \
    } \
    _Pragma("unroll") \
    for (int pp = 0; pp < 4; pp++) { \
        u64* base = pbuf + (size_t)(q * 4 + pp) * 128 + 4 * lane; \
        *(ulonglong2*)(base)     = make_ulonglong2(acc[pp][0], acc[pp][1]); \
        *(ulonglong2*)(base + 2) = make_ulonglong2(acc[pp][2], acc[pp][3]); \
    } \
    __syncthreads(); \
    u64 s0 = bv0, s1 = bv1; \
    _Pragma("unroll") \
    for (int qq = 0; qq < 8; qq++) { \
        const ulonglong2 v = *(const ulonglong2*)(pbuf + (size_t)(qq * 4 + p) * 128 + j0); \
        s0 = fadd2(s0, v.x); s1 = fadd2(s1, v.y); \
    } \
    KOUT[0] = tanh2(s0); KOUT[1] = tanh2(s1); \
} while (0)

#define ODE_PUSH() do { \
    *(ulonglong2*)(xs + p * 128 + j0) = make_ulonglong2(ar[0], ar[1]); \
    __syncthreads(); } while (0)

    for (int st = 0; st < NSTEP; st++) {
        ODE_EVAL(k1);
        {
            const u64 c = dup2(0.2f / 95.0f);
            ar[0] = ffma2(c, k1[0], y0); ar[1] = ffma2(c, k1[1], y1);
        }
        ODE_PUSH();

        ODE_EVAL(k2);
#pragma unroll
        for (int m = 0; m < 2; m++) {
            u64 s = ffma2(dup2(0.225f), k2[m], ffma2(dup2(0.075f), k1[m], (u64)0));
            ar[m] = ffma2(dt2, s, m ? y1 : y0);
        }
        ODE_PUSH();

        ODE_EVAL(k3);
#pragma unroll
        for (int m = 0; m < 2; m++) {
            u64 s = ffma2(dup2(0.9777777777777777f), k1[m], (u64)0);
            s = ffma2(dup2(-3.7333333333333334f), k2[m], s);
            s = ffma2(dup2(3.5555555555555554f), k3[m], s);
            ar[m] = ffma2(dt2, s, m ? y1 : y0);
        }
        ODE_PUSH();

        ODE_EVAL(k4);
#pragma unroll
        for (int m = 0; m < 2; m++) {
            u64 s = ffma2(dup2(2.9525906892141633f), k1[m], (u64)0);
            s = ffma2(dup2(-11.595793324188385f), k2[m], s);
            s = ffma2(dup2(9.822892851699436f), k3[m], s);
            s = ffma2(dup2(-0.2908093278463649f), k4[m], s);
            ar[m] = ffma2(dt2, s, m ? y1 : y0);
        }
        ODE_PUSH();

        ODE_EVAL(k5);
#pragma unroll
        for (int m = 0; m < 2; m++) {
            u64 s = ffma2(dup2(2.8462752525252526f), k1[m], (u64)0);
            s = ffma2(dup2(-10.757575757575758f), k2[m], s);
            s = ffma2(dup2(8.906422717743473f), k3[m], s);
            s = ffma2(dup2(0.2784090909090909f), k4[m], s);
            s = ffma2(dup2(-0.2735313036020583f), k5[m], s);
            ar[m] = ffma2(dt2, s, m ? y1 : y0);
        }
        ODE_PUSH();

        ODE_EVAL(k6);
#pragma unroll
        for (int m = 0; m < 2; m++) {
            u64 s = ffma2(dup2(0.09114583333333333f), k1[m], (u64)0);
            s = ffma2(dup2(0.44923629829290207f), k3[m], s);
            s = ffma2(dup2(0.6510416666666666f), k4[m], s);
            s = ffma2(dup2(-0.322376179245283f), k5[m], s);
            s = ffma2(dup2(0.13095238095238096f), k6[m], s);
            if (m == 0) y0 = ffma2(dt2, s, y0); else y1 = ffma2(dt2, s, y1);
        }
        {
            float c0, d0, c1, d1;
            unpk2(y0, c0, d0); unpk2(y1, c1, d1);
            *(float2*)(g_traj + ((size_t)(st + 1) * BATCH + rowA) * DD + j0) = make_float2(c0, c1);
            *(float2*)(g_traj + ((size_t)(st + 1) * BATCH + rowB) * DD + j0) = make_float2(d0, d1);
        }
        *(ulonglong2*)(xs + p * 128 + j0) = make_ulonglong2(y0, y1);
        __syncthreads();
    }
#undef ODE_EVAL
#undef ODE_PUSH
}

// ---------------------------------------------------------------------------
// Phase 2/4: gi = X @ W_ih^T + b_ih, item-pair f32x2 design.
// 384 thr = 12 warps = 3 gates x 4 item-groups; 12 items (6 pairs) per warp;
// 48-item tiles, x-pairs staged in smem ([k][pair], stride 24 u64).
// ---------------------------------------------------------------------------
__global__ void __launch_bounds__(384)
gi_kernel(const float* __restrict__ X, const float* __restrict__ Wih,
          const float* __restrict__ bih, float* __restrict__ gi)
{
    extern __shared__ float sm[];
    u64* xp = (u64*)(sm + DD * S_GRU);   // [k][pair]: 128*24 u64 = 24KB
    const int tid = threadIdx.x;
    for (int idx = tid; idx < G3 * DD; idx += 384) {
        const int j = idx >> 7, k = idx & 127;
        sm[k * S_GRU + j] = Wih[idx];
    }

    const int lane = tid & 31, w = tid >> 5;
    const int gate = w >> 2, grp = w & 3;
    u64 bv[4];
#pragma unroll
    for (int m = 0; m < 4; m++) bv[m] = dup2(bih[gate * 128 + 4 * lane + m]);
    const float* wb = sm + gate * 128 + 4 * lane;

#pragma unroll 1
    for (int tile = 0; tile < 16; tile++) {
        const int base = blockIdx.x * 768 + tile * 48;
        __syncthreads();   // xp safe to overwrite (also covers weight load, t=0)
        // pack x-pairs: task t: pair = t % 24, quad = t / 24
#pragma unroll
        for (int tt = 0; tt < 2; tt++) {
            const int t = tid + 384 * tt;
            const int pr = t % 24, qd = t / 24;
            const float4 a = *(const float4*)(X + (size_t)(base + 2 * pr) * DD + 4 * qd);
            const float4 b = *(const float4*)(X + (size_t)(base + 2 * pr + 1) * DD + 4 * qd);
            xp[(size_t)(4 * qd + 0) * 24 + pr] = pack2(a.x, b.x);
            xp[(size_t)(4 * qd + 1) * 24 + pr] = pack2(a.y, b.y);
            xp[(size_t)(4 * qd + 2) * 24 + pr] = pack2(a.z, b.z);
            xp[(size_t)(4 * qd + 3) * 24 + pr] = pack2(a.w, b.w);
        }
        __syncthreads();

        u64 acc[6][4];
#pragma unroll
        for (int pp = 0; pp < 6; pp++)
#pragma unroll
            for (int m = 0; m < 4; m++) acc[pp][m] = bv[m];

#pragma unroll 4
        for (int k = 0; k < 128; k++) {
            const float4 wv = *(const float4*)(wb + k * S_GRU);
            const u64 w0 = dup2(wv.x), w1 = dup2(wv.y), w2 = dup2(wv.z), w3 = dup2(wv.w);
            const u64* xk = xp + (size_t)k * 24 + grp * 6;
            const ulonglong2 xA = *(const ulonglong2*)(xk);
            const ulonglong2 xB = *(const ulonglong2*)(xk + 2);
            const ulonglong2 xC = *(const ulonglong2*)(xk + 4);
            acc[0][0]=ffma2(xA.x,w0,acc[0][0]); acc[0][1]=ffma2(xA.x,w1,acc[0][1]);
            acc[0][2]=ffma2(xA.x,w2,acc[0][2]); acc[0][3]=ffma2(xA.x,w3,acc[0][3]);
            acc[1][0]=ffma2(xA.y,w0,acc[1][0]); acc[1][1]=ffma2(xA.y,w1,acc[1][1]);
            acc[1][2]=ffma2(xA.y,w2,acc[1][2]); acc[1][3]=ffma2(xA.y,w3,acc[1][3]);
            acc[2][0]=ffma2(xB.x,w0,acc[2][0]); acc[2][1]=ffma2(xB.x,w1,acc[2][1]);
            acc[2][2]=ffma2(xB.x,w2,acc[2][2]); acc[2][3]=ffma2(xB.x,w3,acc[2][3]);
            acc[3][0]=ffma2(xB.y,w0,acc[3][0]); acc[3][1]=ffma2(xB.y,w1,acc[3][1]);
            acc[3][2]=ffma2(xB.y,w2,acc[3][2]); acc[3][3]=ffma2(xB.y,w3,acc[3][3]);
            acc[4][0]=ffma2(xC.x,w0,acc[4][0]); acc[4][1]=ffma2(xC.x,w1,acc[4][1]);
            acc[4][2]=ffma2(xC.x,w2,acc[4][2]); acc[4][3]=ffma2(xC.x,w3,acc[4][3]);
            acc[5][0]=ffma2(xC.y,w0,acc[5][0]); acc[5][1]=ffma2(xC.y,w1,acc[5][1]);
            acc[5][2]=ffma2(xC.y,w2,acc[5][2]); acc[5][3]=ffma2(xC.y,w3,acc[5][3]);
        }

#pragma unroll
        for (int pp = 0; pp < 6; pp++) {
            const int itemA = base + grp * 12 + 2 * pp;
            float A0,B0,A1,B1,A2,B2,A3,B3;
            unpk2(acc[pp][0], A0, B0); unpk2(acc[pp][1], A1, B1);
            unpk2(acc[pp][2], A2, B2); unpk2(acc[pp][3], A3, B3);
            float* o = gi + (size_t)itemA * G3 + gate * 128 + 4 * lane;
            *(float4*)(o)      = make_float4(A0, A1, A2, A3);
            *(float4*)(o + G3) = make_float4(B0, B1, B2, B3);
        }
    }
}

// ---------------------------------------------------------------------------
// Phase 3/5: GRU scan (exact R6 version). 384 thr, 2 barriers/t.
// ---------------------------------------------------------------------------
__global__ void __launch_bounds__(384)
gru_kernel(const float* __restrict__ gi, const float* __restrict__ Whh,
           const float* __restrict__ bhh, float* __restrict__ otraj,
           float* __restrict__ olast)
{
    extern __shared__ float sm[];
    float* pbuf = sm + DD * S_GRU;
    float* xsf  = pbuf + 6144;
    u64* xsu = (u64*)xsf;
    const int tid = threadIdx.x;
    for (int idx = tid; idx < G3 * DD; idx += 384) {
        const int j = idx >> 7, k = idx & 127;
        sm[k * S_GRU + j] = Whh[idx];
    }
    for (int idx = tid; idx < 2048; idx += 384) xsf[idx] = 0.0f;
    __syncthreads();

    const int lane = tid & 31, wid = tid >> 5;
    const int g = wid >> 2, ks = (wid >> 1) & 1, rh = wid & 1;
    const float* wb = sm + g * 128 + 4 * lane;
    float* pme = pbuf + (size_t)((g * 2 + ks) * 8 + rh * 4) * 128 + 4 * lane;
    const int frow = wid;
    const bool fin = (wid < 8);
    const int grow = blockIdx.x * 8 + frow;

    float br[4], bz[4], bn[4];
    if (fin) {
        const float4 vr = *(const float4*)(bhh + 4 * lane);
        const float4 vz = *(const float4*)(bhh + 128 + 4 * lane);
        const float4 vn = *(const float4*)(bhh + 256 + 4 * lane);
        br[0]=vr.x; br[1]=vr.y; br[2]=vr.z; br[3]=vr.w;
        bz[0]=vz.x; bz[1]=vz.y; bz[2]=vz.z; bz[3]=vz.w;
        bn[0]=vn.x; bn[1]=vn.y; bn[2]=vn.z; bn[3]=vn.w;
    }
    float h[4] = {0.f, 0.f, 0.f, 0.f};

    for (int t = 0; t < TT; t++) {
        float4 gr_, gz_, gn_;
        if (fin) {
            const float* gp = gi + ((size_t)t * BATCH + grow) * G3 + 4 * lane;
            gr_ = *(const float4*)(gp);
            gz_ = *(const float4*)(gp + 128);
            gn_ = *(const float4*)(gp + 256);
        }
        u64 acc[4][2];
#pragma unroll
        for (int r = 0; r < 4; r++) { acc[r][0] = 0; acc[r][1] = 0; }
        const int kbase = 64 * ks;
#pragma unroll 8
        for (int kk = 0; kk < 64; kk += 2) {
            const int k = kbase + kk;
            const ulonglong2 x0 = *(const ulonglong2*)(xsu + (rh * 4 + 0) * 128 + k);
            const ulonglong2 x1 = *(const ulonglong2*)(xsu + (rh * 4 + 1) * 128 + k);
            const ulonglong2 x2 = *(const ulonglong2*)(xsu + (rh * 4 + 2) * 128 + k);
            const ulonglong2 x3 = *(const ulonglong2*)(xsu + (rh * 4 + 3) * 128 + k);
            const ulonglong2 wA = *(const ulonglong2*)(wb + k * S_GRU);
            const ulonglong2 wB = *(const ulonglong2*)(wb + (k + 1) * S_GRU);
            acc[0][0] = ffma2(x0.x, wA.x, acc[0][0]); acc[0][1] = ffma2(x0.x, wA.y, acc[0][1]);
            acc[1][0] = ffma2(x1.x, wA.x, acc[1][0]); acc[1][1] = ffma2(x1.x, wA.y, acc[1][1]);
            acc[2][0] = ffma2(x2.x, wA.x, acc[2][0]); acc[2][1] = ffma2(x2.x, wA.y, acc[2][1]);
            acc[3][0] = ffma2(x3.x, wA.x, acc[3][0]); acc[3][1] = ffma2(x3.x, wA.y, acc[3][1]);
            acc[0][0] = ffma2(x0.y, wB.x, acc[0][0]); acc[0][1] = ffma2(x0.y, wB.y, acc[0][1]);
            acc[1][0] = ffma2(x1.y, wB.x, acc[1][0]); acc[1][1] = ffma2(x1.y, wB.y, acc[1][1]);
            acc[2][0] = ffma2(x2.y, wB.x, acc[2][0]); acc[2][1] = ffma2(x2.y, wB.y, acc[2][1]);
            acc[3][0] = ffma2(x3.y, wB.x, acc[3][0]); acc[3][1] = ffma2(x3.y, wB.y, acc[3][1]);
        }
#pragma unroll
        for (int r = 0; r < 4; r++)
            *(ulonglong2*)(pme + r * 128) = make_ulonglong2(acc[r][0], acc[r][1]);
        __syncthreads();

        if (fin) {
            const float* pb = pbuf + (size_t)frow * 128 + 4 * lane;
            const ulonglong2 pr0 = *(const ulonglong2*)(pb);
            const ulonglong2 pr1 = *(const ulonglong2*)(pb + 8 * 128);
            const ulonglong2 pz0 = *(const ulonglong2*)(pb + 16 * 128);
            const ulonglong2 pz1 = *(const ulonglong2*)(pb + 24 * 128);
            const ulonglong2 pn0 = *(const ulonglong2*)(pb + 32 * 128);
            const ulonglong2 pn1 = *(const ulonglong2*)(pb + 40 * 128);
            float ar[4], az[4], an[4];
            {
                const u64 s0 = fadd2(pr0.x, pr1.x), s1 = fadd2(pr0.y, pr1.y);
                unpk2(s0, ar[0], ar[1]); unpk2(s1, ar[2], ar[3]);
            }
            {
                const u64 s0 = fadd2(pz0.x, pz1.x), s1 = fadd2(pz0.y, pz1.y);
                unpk2(s0, az[0], az[1]); unpk2(s1, az[2], az[3]);
            }
            {
                const u64 s0 = fadd2(pn0.x, pn1.x), s1 = fadd2(pn0.y, pn1.y);
                unpk2(s0, an[0], an[1]); unpk2(s1, an[2], an[3]);
            }
            const float gvr[4] = {gr_.x, gr_.y, gr_.z, gr_.w};
            const float gvz[4] = {gz_.x, gz_.y, gz_.z, gz_.w};
            const float gvn[4] = {gn_.x, gn_.y, gn_.z, gn_.w};
#pragma unroll
            for (int m = 0; m < 4; m++) {
                const float rg = fsigm(gvr[m] + ar[m] + br[m]);
                const float zg = fsigm(gvz[m] + az[m] + bz[m]);
                const float ng = ftanh(gvn[m] + rg * (an[m] + bn[m]));
                h[m] = ng + zg * (h[m] - ng);
            }
            float* xme = xsf + (size_t)(frow * 128 + 4 * lane) * 2;
            *(float4*)(xme)     = make_float4(h[0], h[0], h[1], h[1]);
            *(float4*)(xme + 4) = make_float4(h[2], h[2], h[3], h[3]);
            if (otraj)
                *(float4*)(otraj + ((size_t)t * BATCH + grow) * DD + 4 * lane) =
                    make_float4(h[0], h[1], h[2], h[3]);
        }
        __syncthreads();
    }
    if (olast && fin)
        *(float4*)(olast + (size_t)grow * DD + 4 * lane) =
            make_float4(h[0], h[1], h[2], h[3]);
}

// ---------------------------------------------------------------------------
// Phase 6: FC head (unchanged).
// ---------------------------------------------------------------------------
__global__ void __launch_bounds__(256)
fc_kernel(const float* __restrict__ W1, const float* __restrict__ b1,
          const float* __restrict__ W2, const float* __restrict__ b2,
          float* __restrict__ out)
{
    extern __shared__ float sm[];
    float* hs = sm;
    float* hd = sm + 1024;
    float* wt = sm + 1536;
    const int tid = threadIdx.x;
    const int row0 = blockIdx.x * 8;

    for (int idx = tid; idx < 8 * DD; idx += 256) hs[idx] = g_h2[(size_t)row0 * DD + idx];
    for (int idx = tid; idx < 64 * DD; idx += 256) {
        const int j = idx >> 7, k = idx & 127;
        wt[k * 68 + j] = W1[idx];
    }
    __syncthreads();

#pragma unroll
    for (int i = 0; i < 2; i++) {
        const int p = tid + 256 * i, r = p >> 6, j = p & 63;
        float acc = b1[j];
#pragma unroll 8
        for (int k = 0; k < DD; k++) acc = fmaf(hs[r * DD + k], wt[k * 68 + j], acc);
        hd[r * 64 + j] = acc * normcdff(acc);
    }

    for (int c = 0; c < 12; c++) {
        __syncthreads();
        for (int idx = tid; idx < 256 * 64; idx += 256) {
            const int jj = idx >> 6, k = idx & 63;
            wt[k * 260 + jj] = W2[(size_t)(c * 256 + jj) * 64 + k];
        }
        __syncthreads();
        const int j = c * 256 + tid;
        float acc[8];
#pragma unroll
        for (int r = 0; r < 8; r++) acc[r] = b2[j];
#pragma unroll 8
        for (int k = 0; k < 64; k++) {
            const float w = wt[k * 260 + tid];
#pragma unroll
            for (int r = 0; r < 8; r++) acc[r] = fmaf(hd[r * 64 + k], w, acc[r]);
        }
#pragma unroll
        for (int r = 0; r < 8; r++) out[(size_t)(row0 + r) * 3072 + j] = acc[r];
    }
}

// ---------------------------------------------------------------------------
extern "C" void kernel_launch(void* const* d_in, const int* in_sizes, int n_in,
                              void* d_out, int out_size)
{
    (void)in_sizes; (void)n_in; (void)out_size;
    const float* yl    = (const float*)d_in[1];
    const float* yh    = (const float*)d_in[2];
    const float* W_ode = (const float*)d_in[3];
    const float* b_ode = (const float*)d_in[4];
    const float* W_ih0 = (const float*)d_in[5];
    const float* W_hh0 = (const float*)d_in[6];
    const float* b_ih0 = (const float*)d_in[7];
    const float* b_hh0 = (const float*)d_in[8];
    const float* W_ih1 = (const float*)d_in[9];
    const float* W_hh1 = (const float*)d_in[10];
    const float* b_ih1 = (const float*)d_in[11];
    const float* b_hh1 = (const float*)d_in[12];
    const float* W1    = (const float*)d_in[13];
    const float* b1    = (const float*)d_in[14];
    const float* W2    = (const float*)d_in[15];
    const float* b2    = (const float*)d_in[16];
    float* out = (float*)d_out;

    float *traj, *gibuf, *h1, *h2;
    cudaGetSymbolAddress((void**)&traj,  g_traj);
    cudaGetSymbolAddress((void**)&gibuf, g_gi);
    cudaGetSymbolAddress((void**)&h1,    g_h1);
    cudaGetSymbolAddress((void**)&h2,    g_h2);

    const int SM_ODE  = S_ODE * DD * 4 + 32768 + 4096;    // 104,448 B
    const int SM_GI   = S_GRU * DD * 4 + 24576;           // 223,232 B
    const int SM_GRU2 = (S_GRU * DD + 6144 + 2048) * 4;   // 231,424 B
    const int SM_FC   = (1536 + 64 * 260) * 4;            //  72,704 B
    cudaFuncSetAttribute(ode_kernel, cudaFuncAttributeMaxDynamicSharedMemorySize, SM_ODE);
    cudaFuncSetAttribute(gi_kernel,  cudaFuncAttributeMaxDynamicSharedMemorySize, SM_GI);
    cudaFuncSetAttribute(gru_kernel, cudaFuncAttributeMaxDynamicSharedMemorySize, SM_GRU2);
    cudaFuncSetAttribute(fc_kernel,  cudaFuncAttributeMaxDynamicSharedMemorySize, SM_FC);

    ode_kernel<<<128, 256, SM_ODE>>>(yl, yh, W_ode, b_ode);
    gi_kernel <<<128, 384, SM_GI>>>(traj, W_ih0, b_ih0, gibuf);
    gru_kernel<<<128, 384, SM_GRU2>>>(gibuf, W_hh0, b_hh0, h1, nullptr);
    gi_kernel <<<128, 384, SM_GI>>>(h1, W_ih1, b_ih1, gibuf);
    gru_kernel<<<128, 384, SM_GRU2>>>(gibuf, W_hh1, b_hh1, nullptr, h2);
    fc_kernel <<<128, 256, SM_FC>>>(W1, b1, W2, b2, out);
}